// round 1
// baseline (speedup 1.0000x reference)
#include <cuda_runtime.h>

// SplitMLP: per group g (G=10000):
//   h[b,:]  = relu( W1_day[g] @ day[b] + W1_var[g] @ items[b,g] + b1[g] )   (64)
//   y[b,:]  = W2[g] @ h[b,:] + b2[g]                                        (4)
// Shapes: day[128][16], items[128][10000][32], W1_day[G][64][16],
//         W1_var[G][64][32], b1[G][64], W2[G][4][64], b2[G][4],
//         out[128][10000][4] (fp32)

#define B_   128
#define C_   16
#define V_   32
#define H_   64
#define O_   4
#define G_   10000
#define K_   48            // C_ + V_

#define SA_STRIDE 132      // padded row stride of A_T (floats), 16B-aligned rows
#define SW_STRIDE 68       // padded row stride of Wcat (floats), 16B-aligned rows

__global__ __launch_bounds__(256, 3)
void splitmlp_kernel(const float* __restrict__ day,
                     const float* __restrict__ items,
                     const float* __restrict__ W1_day,
                     const float* __restrict__ W1_var,
                     const float* __restrict__ b1,
                     const float* __restrict__ W2,
                     const float* __restrict__ b2,
                     float* __restrict__ out)
{
    __shared__ __align__(16) float sA[K_ * SA_STRIDE];   // A_T[k][b]  (48 x 128, padded)
    __shared__ __align__(16) float sW[K_ * SW_STRIDE];   // Wcat[k][h] (48 x 64, padded)
    __shared__ __align__(16) float sW2[O_ * H_];         // W2[o][h]   (4 x 64)
    __shared__ float sB1[H_];
    __shared__ float sB2[O_];

    const int tid = threadIdx.x;
    const int g   = blockIdx.x;

    // ---- Stage A_T rows 0..15 : day (transposed) -------------------------
    #pragma unroll
    for (int i = tid; i < (B_ * C_) / 4; i += 256) {        // 512 float4
        int b  = i >> 2;
        int c4 = i & 3;
        float4 v = *(const float4*)(day + b * C_ + c4 * 4);
        sA[(c4 * 4 + 0) * SA_STRIDE + b] = v.x;
        sA[(c4 * 4 + 1) * SA_STRIDE + b] = v.y;
        sA[(c4 * 4 + 2) * SA_STRIDE + b] = v.z;
        sA[(c4 * 4 + 3) * SA_STRIDE + b] = v.w;
    }
    // ---- Stage A_T rows 16..47 : items[:,g,:] (transposed) ---------------
    #pragma unroll
    for (int i = tid; i < (B_ * V_) / 4; i += 256) {        // 1024 float4
        int b  = i >> 3;
        int v4 = i & 7;
        float4 v = *(const float4*)(items + ((size_t)b * G_ + g) * V_ + v4 * 4);
        sA[(C_ + v4 * 4 + 0) * SA_STRIDE + b] = v.x;
        sA[(C_ + v4 * 4 + 1) * SA_STRIDE + b] = v.y;
        sA[(C_ + v4 * 4 + 2) * SA_STRIDE + b] = v.z;
        sA[(C_ + v4 * 4 + 3) * SA_STRIDE + b] = v.w;
    }
    // ---- Stage Wcat rows 0..15 : W1_day[g] (transposed) ------------------
    {
        int i  = tid;                                       // exactly 256 float4
        int h  = i >> 2;
        int c4 = i & 3;
        float4 v = *(const float4*)(W1_day + (size_t)g * H_ * C_ + h * C_ + c4 * 4);
        sW[(c4 * 4 + 0) * SW_STRIDE + h] = v.x;
        sW[(c4 * 4 + 1) * SW_STRIDE + h] = v.y;
        sW[(c4 * 4 + 2) * SW_STRIDE + h] = v.z;
        sW[(c4 * 4 + 3) * SW_STRIDE + h] = v.w;
    }
    // ---- Stage Wcat rows 16..47 : W1_var[g] (transposed) -----------------
    #pragma unroll
    for (int i = tid; i < (H_ * V_) / 4; i += 256) {        // 512 float4
        int h  = i >> 3;
        int v4 = i & 7;
        float4 v = *(const float4*)(W1_var + (size_t)g * H_ * V_ + h * V_ + v4 * 4);
        sW[(C_ + v4 * 4 + 0) * SW_STRIDE + h] = v.x;
        sW[(C_ + v4 * 4 + 1) * SW_STRIDE + h] = v.y;
        sW[(C_ + v4 * 4 + 2) * SW_STRIDE + h] = v.z;
        sW[(C_ + v4 * 4 + 3) * SW_STRIDE + h] = v.w;
    }
    // ---- Stage W2, b1, b2 ------------------------------------------------
    if (tid < (O_ * H_) / 4) {                              // 64 float4
        *(float4*)&sW2[tid * 4] =
            *(const float4*)(W2 + (size_t)g * O_ * H_ + tid * 4);
    }
    if (tid < H_) sB1[tid] = b1[(size_t)g * H_ + tid];
    if (tid < O_) sB2[tid] = b2[(size_t)g * O_ + tid];

    __syncthreads();

    // ---- fc1: each thread owns a 4(b) x 8(h) fp32 tile -------------------
    const int bt = tid >> 3;   // 0..31  -> rows b = bt*4 .. bt*4+3
    const int ht = tid & 7;    // 0..7   -> cols h = ht*8 .. ht*8+7

    float acc[4][8];
    #pragma unroll
    for (int i = 0; i < 8; i++) {
        float bv = sB1[ht * 8 + i];
        acc[0][i] = bv; acc[1][i] = bv; acc[2][i] = bv; acc[3][i] = bv;
    }

    #pragma unroll 4
    for (int k = 0; k < K_; k++) {
        float4 a  = *(const float4*)&sA[k * SA_STRIDE + bt * 4];
        float4 w0 = *(const float4*)&sW[k * SW_STRIDE + ht * 8];
        float4 w1 = *(const float4*)&sW[k * SW_STRIDE + ht * 8 + 4];
        float av[4] = {a.x, a.y, a.z, a.w};
        float wv[8] = {w0.x, w0.y, w0.z, w0.w, w1.x, w1.y, w1.z, w1.w};
        #pragma unroll
        for (int bb = 0; bb < 4; bb++)
            #pragma unroll
            for (int i = 0; i < 8; i++)
                acc[bb][i] = fmaf(av[bb], wv[i], acc[bb][i]);
    }

    // ReLU
    #pragma unroll
    for (int bb = 0; bb < 4; bb++)
        #pragma unroll
        for (int i = 0; i < 8; i++)
            acc[bb][i] = fmaxf(acc[bb][i], 0.0f);

    // ---- fc2: partials over this thread's 8 h-cols, then shfl-reduce -----
    float p[4][O_];
    #pragma unroll
    for (int o = 0; o < O_; o++) {
        float4 wa = *(const float4*)&sW2[o * H_ + ht * 8];
        float4 wb = *(const float4*)&sW2[o * H_ + ht * 8 + 4];
        float wv[8] = {wa.x, wa.y, wa.z, wa.w, wb.x, wb.y, wb.z, wb.w};
        #pragma unroll
        for (int bb = 0; bb < 4; bb++) {
            float s = 0.0f;
            #pragma unroll
            for (int i = 0; i < 8; i++)
                s = fmaf(acc[bb][i], wv[i], s);
            p[bb][o] = s;
        }
    }

    // Reduce across the 8 ht-lanes (lane bits 0..2)
    #pragma unroll
    for (int m = 1; m < 8; m <<= 1)
        #pragma unroll
        for (int bb = 0; bb < 4; bb++)
            #pragma unroll
            for (int o = 0; o < O_; o++)
                p[bb][o] += __shfl_xor_sync(0xffffffffu, p[bb][o], m);

    if (ht == 0) {
        #pragma unroll
        for (int bb = 0; bb < 4; bb++) {
            int b = bt * 4 + bb;
            float4 y;
            y.x = p[bb][0] + sB2[0];
            y.y = p[bb][1] + sB2[1];
            y.z = p[bb][2] + sB2[2];
            y.w = p[bb][3] + sB2[3];
            *(float4*)&out[((size_t)b * G_ + g) * O_] = y;
        }
    }
}

extern "C" void kernel_launch(void* const* d_in, const int* in_sizes, int n_in,
                              void* d_out, int out_size)
{
    const float* day    = (const float*)d_in[0];
    const float* items  = (const float*)d_in[1];
    const float* W1_day = (const float*)d_in[2];
    const float* W1_var = (const float*)d_in[3];
    const float* b1     = (const float*)d_in[4];
    const float* W2     = (const float*)d_in[5];
    const float* b2     = (const float*)d_in[6];
    float* out = (float*)d_out;

    splitmlp_kernel<<<G_, 256>>>(day, items, W1_day, W1_var, b1, W2, b2, out);
}

// round 5
// speedup vs baseline: 3.5009x; 3.5009x over previous
#include <cuda_runtime.h>
#include <cstdint>

// SplitMLP via tf32 mma.sync (sm_80 baseline path — tcgen05 PTX is rejected by
// this harness's nvcc target).
// Per group g: h = relu(A @ Wcat^T + b1); y = h @ W2^T + b2
//   A    = [day | items[:,g,:]] : 128 x 48, K-major (natural layout, no transpose)
//   Wcat = [W1_day | W1_var][g]: 64 x 48,  K-major (natural layout)
// fc1 on tensor cores (tf32, fp32 accum); bias+ReLU+fc2 in fp32 registers.

#define B_ 128
#define C_ 16
#define V_ 32
#define H_ 64
#define O_ 4
#define G_ 10000
#define KS_ 52          // padded row stride (floats): 208B, 16B-aligned, ldmatrix conflict-free

__device__ __forceinline__ uint32_t s2u(const void* p) {
    uint32_t a;
    asm("{ .reg .u64 t; cvta.to.shared.u64 t, %1; cvt.u32.u64 %0, t; }"
        : "=r"(a) : "l"(p));
    return a;
}

__device__ __forceinline__ uint32_t f2tf(float f) {
    uint32_t r;
    asm("cvt.rna.tf32.f32 %0, %1;" : "=r"(r) : "f"(f));
    return r;
}

__device__ __forceinline__ void ldsm4(uint32_t& r0, uint32_t& r1,
                                      uint32_t& r2, uint32_t& r3, uint32_t addr) {
    asm volatile("ldmatrix.sync.aligned.m8n8.x4.shared.b16 {%0,%1,%2,%3}, [%4];"
                 : "=r"(r0), "=r"(r1), "=r"(r2), "=r"(r3) : "r"(addr));
}

__device__ __forceinline__ void mma_tf32(float* d, const uint32_t* a, const uint32_t* b) {
    asm volatile(
        "mma.sync.aligned.m16n8k8.row.col.f32.tf32.tf32.f32 "
        "{%0,%1,%2,%3}, {%4,%5,%6,%7}, {%8,%9}, {%0,%1,%2,%3};"
        : "+f"(d[0]), "+f"(d[1]), "+f"(d[2]), "+f"(d[3])
        : "r"(a[0]), "r"(a[1]), "r"(a[2]), "r"(a[3]), "r"(b[0]), "r"(b[1]));
}

// convert float4 -> tf32, store 16B to smem row-major [row][k0..k0+3]
__device__ __forceinline__ void stage4(uint32_t* base, int row, int k0, float4 v) {
    uint4 t;
    t.x = f2tf(v.x); t.y = f2tf(v.y); t.z = f2tf(v.z); t.w = f2tf(v.w);
    *(uint4*)(base + row * KS_ + k0) = t;
}

__global__ __launch_bounds__(128, 4)
void splitmlp_tf32_kernel(const float* __restrict__ day,
                          const float* __restrict__ items,
                          const float* __restrict__ W1_day,
                          const float* __restrict__ W1_var,
                          const float* __restrict__ b1,
                          const float* __restrict__ W2,
                          const float* __restrict__ b2,
                          float* __restrict__ out)
{
    __shared__ __align__(16) uint32_t sA[B_ * KS_];   // A  (tf32), rows=b, 26624 B
    __shared__ __align__(16) uint32_t sB[H_ * KS_];   // Wcat (tf32), rows=h, 13312 B
    __shared__ __align__(16) float sW2[O_ * H_];
    __shared__ __align__(16) float sB1[H_];
    __shared__ __align__(16) float sB2[O_];

    const int tid  = threadIdx.x;
    const int lane = tid & 31;
    const int wid  = tid >> 5;
    const int g    = blockIdx.x;

    // ---- Stage A: day -> k 0..15, items[:,g,:] -> k 16..47 ----------------
    #pragma unroll
    for (int i = tid; i < 512; i += 128) {            // day: 128 rows x 4 float4
        int b = i >> 2, c4 = i & 3;
        float4 v = *(const float4*)(day + b * C_ + c4 * 4);
        stage4(sA, b, c4 * 4, v);
    }
    #pragma unroll
    for (int i = tid; i < 1024; i += 128) {           // items: 128 rows x 8 float4
        int b = i >> 3, v4 = i & 7;
        float4 v = *(const float4*)(items + ((size_t)b * G_ + g) * V_ + v4 * 4);
        stage4(sA, b, C_ + v4 * 4, v);
    }
    // ---- Stage B = Wcat ----------------------------------------------------
    #pragma unroll
    for (int i = tid; i < 256; i += 128) {            // W1_day: 64 rows x 4 float4
        int h = i >> 2, c4 = i & 3;
        float4 v = *(const float4*)(W1_day + (size_t)g * H_ * C_ + h * C_ + c4 * 4);
        stage4(sB, h, c4 * 4, v);
    }
    #pragma unroll
    for (int i = tid; i < 512; i += 128) {            // W1_var: 64 rows x 8 float4
        int h = i >> 3, v4 = i & 7;
        float4 v = *(const float4*)(W1_var + (size_t)g * H_ * V_ + h * V_ + v4 * 4);
        stage4(sB, h, C_ + v4 * 4, v);
    }
    // ---- Stage W2 / b1 / b2 (fp32) ----------------------------------------
    if (tid < 64)
        *(float4*)&sW2[tid * 4] = *(const float4*)(W2 + (size_t)g * O_ * H_ + tid * 4);
    if (tid < 64)
        sB1[tid] = b1[(size_t)g * H_ + tid];
    if (tid < 4)
        sB2[tid] = b2[(size_t)g * O_ + tid];

    __syncthreads();

    // ---- fc1 mainloop: warp w computes rows 32w..32w+31, all 64 cols -------
    // ldmatrix address (b16 view of tf32 tiles):
    //   row = base + (lane&15), +16B for lanes 16..31 (covers tf32 cols +4)
    uint32_t aBase = s2u(sA) + ((32 * wid + (lane & 15)) * KS_ + (lane >> 4) * 4) * 4;
    uint32_t bBase = s2u(sB) + (((lane & 15)) * KS_ + (lane >> 4) * 4) * 4;

    float acc[2][8][4];
    #pragma unroll
    for (int mt = 0; mt < 2; mt++)
        #pragma unroll
        for (int nt = 0; nt < 8; nt++)
            #pragma unroll
            for (int c = 0; c < 4; c++)
                acc[mt][nt][c] = 0.0f;

    #pragma unroll
    for (int ks = 0; ks < 6; ks++) {                  // K = 48 = 6 x 8
        uint32_t a[2][4];
        ldsm4(a[0][0], a[0][1], a[0][2], a[0][3], aBase + ks * 32);
        ldsm4(a[1][0], a[1][1], a[1][2], a[1][3], aBase + 16 * KS_ * 4 + ks * 32);

        uint32_t bf[8][2];
        #pragma unroll
        for (int np = 0; np < 4; np++) {              // 16 n-rows per ldmatrix.x4
            uint32_t r0, r1, r2, r3;
            ldsm4(r0, r1, r2, r3, bBase + np * 16 * KS_ * 4 + ks * 32);
            bf[2 * np + 0][0] = r0; bf[2 * np + 0][1] = r2;
            bf[2 * np + 1][0] = r1; bf[2 * np + 1][1] = r3;
        }

        #pragma unroll
        for (int mt = 0; mt < 2; mt++)
            #pragma unroll
            for (int nt = 0; nt < 8; nt++)
                mma_tf32(acc[mt][nt], a[mt], bf[nt]);
    }

    // ---- Epilogue: bias + ReLU + fc2, all in registers ---------------------
    // Lane holds rows {32w + 16mt + (lane>>2) + 8hh}, cols {8nt + 2(lane&3) +{0,1}}.
    float y[4][4];                                     // [mt*2+hh][o]
    #pragma unroll
    for (int j = 0; j < 4; j++)
        #pragma unroll
        for (int o = 0; o < O_; o++)
            y[j][o] = 0.0f;

    #pragma unroll
    for (int nt = 0; nt < 8; nt++) {
        const int h0 = nt * 8 + 2 * (lane & 3);
        float2 bb = *(const float2*)&sB1[h0];
        float2 w0 = *(const float2*)&sW2[0 * H_ + h0];
        float2 w1 = *(const float2*)&sW2[1 * H_ + h0];
        float2 w2 = *(const float2*)&sW2[2 * H_ + h0];
        float2 w3 = *(const float2*)&sW2[3 * H_ + h0];
        #pragma unroll
        for (int mt = 0; mt < 2; mt++)
            #pragma unroll
            for (int hh = 0; hh < 2; hh++) {
                float v0 = fmaxf(acc[mt][nt][hh * 2 + 0] + bb.x, 0.0f);
                float v1 = fmaxf(acc[mt][nt][hh * 2 + 1] + bb.y, 0.0f);
                const int j = mt * 2 + hh;
                y[j][0] = fmaf(v0, w0.x, fmaf(v1, w0.y, y[j][0]));
                y[j][1] = fmaf(v0, w1.x, fmaf(v1, w1.y, y[j][1]));
                y[j][2] = fmaf(v0, w2.x, fmaf(v1, w2.y, y[j][2]));
                y[j][3] = fmaf(v0, w3.x, fmaf(v1, w3.y, y[j][3]));
            }
    }

    // Reduce over the 4 lanes sharing a row (lane bits 0..1)
    #pragma unroll
    for (int m = 1; m < 4; m <<= 1)
        #pragma unroll
        for (int j = 0; j < 4; j++)
            #pragma unroll
            for (int o = 0; o < O_; o++)
                y[j][o] += __shfl_xor_sync(0xffffffffu, y[j][o], m);

    if ((lane & 3) == 0) {
        const int r = lane >> 2;                       // 0..7
        #pragma unroll
        for (int mt = 0; mt < 2; mt++)
            #pragma unroll
            for (int hh = 0; hh < 2; hh++) {
                const int j = mt * 2 + hh;
                const int b = 32 * wid + 16 * mt + 8 * hh + r;
                float4 o4;
                o4.x = y[j][0] + sB2[0];
                o4.y = y[j][1] + sB2[1];
                o4.z = y[j][2] + sB2[2];
                o4.w = y[j][3] + sB2[3];
                *(float4*)(out + ((size_t)b * G_ + g) * O_) = o4;
            }
    }
}

extern "C" void kernel_launch(void* const* d_in, const int* in_sizes, int n_in,
                              void* d_out, int out_size)
{
    const float* day    = (const float*)d_in[0];
    const float* items  = (const float*)d_in[1];
    const float* W1_day = (const float*)d_in[2];
    const float* W1_var = (const float*)d_in[3];
    const float* b1     = (const float*)d_in[4];
    const float* W2     = (const float*)d_in[5];
    const float* b2     = (const float*)d_in[6];
    float* out = (float*)d_out;

    splitmlp_tf32_kernel<<<G_, 128>>>(day, items, W1_day, W1_var, b1, W2, b2, out);
}

// round 7
// speedup vs baseline: 3.6636x; 1.0465x over previous
#include <cuda_runtime.h>
#include <cstdint>

// SplitMLP, tf32 mma.sync + persistent CTAs + double-buffered cp.async pipeline.
// Per group g: h = relu(A @ Wcat^T + b1); y = h @ W2^T + b2
//   A    = [day | items[:,g,:]] : 128 x 48 K-major  (day staged once, static)
//   Wcat = [W1_day | W1_var][g]: 64 x 48  K-major
// fc1 on tensor cores (tf32, fp32 accum), bias+ReLU+fc2 in fp32 registers.

#define B_ 128
#define C_ 16
#define V_ 32
#define H_ 64
#define O_ 4
#define G_ 10000

#define THREADS 128
#define GRID 296            // 2 CTAs/SM x 148 SMs, persistent

// smem row strides (floats) — all verified ldmatrix-phase conflict-free
#define KS_D 20             // day   tile: 128 x 16  (80B rows)
#define KS_I 36             // items tile: 128 x 32  (144B rows)
#define KS_B 52             // Wcat  tile:  64 x 48  (208B rows)

#define SZ_DAY (B_ * KS_D * 4)              // 10240
#define SZ_AI  (B_ * KS_I * 4)              // 18432
#define SZ_B   (H_ * KS_B * 4)              // 13312
#define SZ_W2  (O_ * H_ * 4)                // 1024
#define SZ_B1  (H_ * 4)                     // 256
#define SZ_B2  16
#define BUF_SZ (SZ_AI + SZ_B + SZ_W2 + SZ_B1 + SZ_B2)   // 33040
#define SMEM_TOTAL (SZ_DAY + 2 * BUF_SZ)                 // 76320

__device__ __forceinline__ uint32_t s2u(const void* p) {
    uint32_t a;
    asm("{ .reg .u64 t; cvta.to.shared.u64 t, %1; cvt.u32.u64 %0, t; }"
        : "=r"(a) : "l"(p));
    return a;
}

__device__ __forceinline__ void cpa16(uint32_t dst, const void* src) {
    asm volatile("cp.async.cg.shared.global [%0], [%1], 16;"
                 :: "r"(dst), "l"(src) : "memory");
}

__device__ __forceinline__ void ldsm4(uint32_t& r0, uint32_t& r1,
                                      uint32_t& r2, uint32_t& r3, uint32_t addr) {
    asm volatile("ldmatrix.sync.aligned.m8n8.x4.shared.b16 {%0,%1,%2,%3}, [%4];"
                 : "=r"(r0), "=r"(r1), "=r"(r2), "=r"(r3) : "r"(addr));
}

__device__ __forceinline__ void mma_tf32(float* d, const uint32_t* a, const uint32_t* b) {
    asm volatile(
        "mma.sync.aligned.m16n8k8.row.col.f32.tf32.tf32.f32 "
        "{%0,%1,%2,%3}, {%4,%5,%6,%7}, {%8,%9}, {%0,%1,%2,%3};"
        : "+f"(d[0]), "+f"(d[1]), "+f"(d[2]), "+f"(d[3])
        : "r"(a[0]), "r"(a[1]), "r"(a[2]), "r"(a[3]), "r"(b[0]), "r"(b[1]));
}

// stage one group's per-group data (items, W1_day, W1_var, W2, b1, b2) async
__device__ __forceinline__ void stage_group(
    uint32_t bufU, int g, int tid,
    const float* __restrict__ items, const float* __restrict__ W1_day,
    const float* __restrict__ W1_var, const float* __restrict__ W2,
    const float* __restrict__ b1, const float* __restrict__ b2)
{
    // items: 128 rows x 8 granules -> A-items tile (k local 0..31)
    #pragma unroll
    for (int i = tid; i < 1024; i += THREADS) {
        int b = i >> 3, v4 = i & 7;
        cpa16(bufU + b * (KS_I * 4) + v4 * 16,
              items + ((size_t)b * G_ + g) * V_ + v4 * 4);
    }
    const uint32_t bB = bufU + SZ_AI;
    // W1_day -> Wcat cols 0..15
    #pragma unroll
    for (int i = tid; i < 256; i += THREADS) {
        int h = i >> 2, c4 = i & 3;
        cpa16(bB + h * (KS_B * 4) + c4 * 16,
              W1_day + (size_t)g * H_ * C_ + h * C_ + c4 * 4);
    }
    // W1_var -> Wcat cols 16..47
    #pragma unroll
    for (int i = tid; i < 512; i += THREADS) {
        int h = i >> 3, v4 = i & 7;
        cpa16(bB + h * (KS_B * 4) + 64 + v4 * 16,
              W1_var + (size_t)g * H_ * V_ + h * V_ + v4 * 4);
    }
    const uint32_t bW2 = bufU + SZ_AI + SZ_B;
    if (tid < 64) {
        cpa16(bW2 + tid * 16, W2 + (size_t)g * O_ * H_ + tid * 4);
    } else if (tid < 80) {
        cpa16(bW2 + SZ_W2 + (tid - 64) * 16, b1 + (size_t)g * H_ + (tid - 64) * 4);
    } else if (tid == 80) {
        cpa16(bW2 + SZ_W2 + SZ_B1, b2 + (size_t)g * O_);
    }
}

__global__ void __launch_bounds__(THREADS)
splitmlp_pipe_kernel(const float* __restrict__ day,
                     const float* __restrict__ items,
                     const float* __restrict__ W1_day,
                     const float* __restrict__ W1_var,
                     const float* __restrict__ b1,
                     const float* __restrict__ W2,
                     const float* __restrict__ b2,
                     float* __restrict__ out)
{
    extern __shared__ __align__(128) char sm[];
    const uint32_t sbase = s2u(sm);
    const uint32_t dayU  = sbase;
    const int tid  = threadIdx.x;
    const int lane = tid & 31;
    const int wid  = tid >> 5;

    // ---- stage day once (joins the first async group) ----
    #pragma unroll
    for (int i = tid; i < 512; i += THREADS) {
        int b = i >> 2, c4 = i & 3;
        cpa16(dayU + b * (KS_D * 4) + c4 * 16, day + b * C_ + c4 * 4);
    }

    const int g0 = blockIdx.x;
    if (g0 >= G_) return;

    // ---- prologue: stage first group into buffer 0 ----
    stage_group(sbase + SZ_DAY, g0, tid, items, W1_day, W1_var, W2, b1, b2);
    asm volatile("cp.async.commit_group;" ::: "memory");

    // ldmatrix base addresses (b16 view of tf32 tiles)
    const int rsel = lane & 15, hsel = (lane >> 4) * 16;
    const uint32_t dayAddr = dayU + (32 * wid + rsel) * (KS_D * 4) + hsel;

    int it = 0;
    for (int g = g0; g < G_; g += GRID, it++) {
        const uint32_t curU = sbase + SZ_DAY + (uint32_t)(it & 1) * BUF_SZ;
        const char*    curP = sm + SZ_DAY + (size_t)(it & 1) * BUF_SZ;

        const int gn = g + GRID;
        if (gn < G_) {
            stage_group(sbase + SZ_DAY + (uint32_t)((it + 1) & 1) * BUF_SZ,
                        gn, tid, items, W1_day, W1_var, W2, b1, b2);
            asm volatile("cp.async.commit_group;" ::: "memory");
            asm volatile("cp.async.wait_group 1;" ::: "memory");
        } else {
            asm volatile("cp.async.wait_group 0;" ::: "memory");
        }
        __syncthreads();

        // ---- fc1 mainloop: warp owns rows 32w..32w+31, all 64 cols ----
        const uint32_t aiAddr = curU + (32 * wid + rsel) * (KS_I * 4) + hsel;
        const uint32_t bAddr  = curU + SZ_AI + rsel * (KS_B * 4) + hsel;

        float acc[2][8][4];
        #pragma unroll
        for (int mt = 0; mt < 2; mt++)
            #pragma unroll
            for (int nt = 0; nt < 8; nt++)
                #pragma unroll
                for (int c = 0; c < 4; c++)
                    acc[mt][nt][c] = 0.0f;

        #pragma unroll
        for (int ks = 0; ks < 6; ks++) {               // K = 48 = 6 x 8
            uint32_t a[2][4];
            if (ks < 2) {                              // day part (k 0..15)
                ldsm4(a[0][0], a[0][1], a[0][2], a[0][3], dayAddr + ks * 32);
                ldsm4(a[1][0], a[1][1], a[1][2], a[1][3],
                      dayAddr + 16 * (KS_D * 4) + ks * 32);
            } else {                                   // items part (k 16..47)
                ldsm4(a[0][0], a[0][1], a[0][2], a[0][3], aiAddr + (ks - 2) * 32);
                ldsm4(a[1][0], a[1][1], a[1][2], a[1][3],
                      aiAddr + 16 * (KS_I * 4) + (ks - 2) * 32);
            }
            uint32_t bf[8][2];
            #pragma unroll
            for (int np = 0; np < 4; np++) {
                uint32_t r0, r1, r2, r3;
                ldsm4(r0, r1, r2, r3, bAddr + np * 16 * (KS_B * 4) + ks * 32);
                bf[2 * np + 0][0] = r0; bf[2 * np + 0][1] = r2;
                bf[2 * np + 1][0] = r1; bf[2 * np + 1][1] = r3;
            }
            #pragma unroll
            for (int mt = 0; mt < 2; mt++)
                #pragma unroll
                for (int nt = 0; nt < 8; nt++)
                    mma_tf32(acc[mt][nt], a[mt], bf[nt]);
        }

        // ---- epilogue: bias + ReLU + fc2 in registers ----
        const float* W2s = (const float*)(curP + SZ_AI + SZ_B);
        const float* b1s = (const float*)(curP + SZ_AI + SZ_B + SZ_W2);
        const float* b2s = (const float*)(curP + SZ_AI + SZ_B + SZ_W2 + SZ_B1);

        float y[4][4];
        #pragma unroll
        for (int j = 0; j < 4; j++)
            #pragma unroll
            for (int o = 0; o < O_; o++)
                y[j][o] = 0.0f;

        #pragma unroll
        for (int nt = 0; nt < 8; nt++) {
            const int h0 = nt * 8 + 2 * (lane & 3);
            float2 bb = *(const float2*)&b1s[h0];
            float2 w0 = *(const float2*)&W2s[0 * H_ + h0];
            float2 w1 = *(const float2*)&W2s[1 * H_ + h0];
            float2 w2 = *(const float2*)&W2s[2 * H_ + h0];
            float2 w3 = *(const float2*)&W2s[3 * H_ + h0];
            #pragma unroll
            for (int mt = 0; mt < 2; mt++)
                #pragma unroll
                for (int hh = 0; hh < 2; hh++) {
                    float v0 = fmaxf(acc[mt][nt][hh * 2 + 0] + bb.x, 0.0f);
                    float v1 = fmaxf(acc[mt][nt][hh * 2 + 1] + bb.y, 0.0f);
                    const int j = mt * 2 + hh;
                    y[j][0] = fmaf(v0, w0.x, fmaf(v1, w0.y, y[j][0]));
                    y[j][1] = fmaf(v0, w1.x, fmaf(v1, w1.y, y[j][1]));
                    y[j][2] = fmaf(v0, w2.x, fmaf(v1, w2.y, y[j][2]));
                    y[j][3] = fmaf(v0, w3.x, fmaf(v1, w3.y, y[j][3]));
                }
        }

        #pragma unroll
        for (int m = 1; m < 4; m <<= 1)
            #pragma unroll
            for (int j = 0; j < 4; j++)
                #pragma unroll
                for (int o = 0; o < O_; o++)
                    y[j][o] += __shfl_xor_sync(0xffffffffu, y[j][o], m);

        if ((lane & 3) == 0) {
            const int r = lane >> 2;
            #pragma unroll
            for (int mt = 0; mt < 2; mt++)
                #pragma unroll
                for (int hh = 0; hh < 2; hh++) {
                    const int j = mt * 2 + hh;
                    const int b = 32 * wid + 16 * mt + 8 * hh + r;
                    float4 o4;
                    o4.x = y[j][0] + b2s[0];
                    o4.y = y[j][1] + b2s[1];
                    o4.z = y[j][2] + b2s[2];
                    o4.w = y[j][3] + b2s[3];
                    *(float4*)(out + ((size_t)b * G_ + g) * O_) = o4;
                }
        }

        __syncthreads();   // buffer reuse: next-next stage writes over this one
    }
}

extern "C" void kernel_launch(void* const* d_in, const int* in_sizes, int n_in,
                              void* d_out, int out_size)
{
    const float* day    = (const float*)d_in[0];
    const float* items  = (const float*)d_in[1];
    const float* W1_day = (const float*)d_in[2];
    const float* W1_var = (const float*)d_in[3];
    const float* b1     = (const float*)d_in[4];
    const float* W2     = (const float*)d_in[5];
    const float* b2     = (const float*)d_in[6];
    float* out = (float*)d_out;

    static bool attr_done = false;
    if (!attr_done) {
        cudaFuncSetAttribute(splitmlp_pipe_kernel,
                             cudaFuncAttributeMaxDynamicSharedMemorySize, SMEM_TOTAL);
        attr_done = true;
    }
    splitmlp_pipe_kernel<<<GRID, THREADS, SMEM_TOTAL>>>(
        day, items, W1_day, W1_var, b1, W2, b2, out);
}